// round 4
// baseline (speedup 1.0000x reference)
#include <cuda_runtime.h>
#include <cstdint>

#define N_NODES 100000
#define N_EDGES 1600000
#define D 128
#define SCAN_BLK 1024
#define N_SCAN_BLOCKS ((N_NODES + SCAN_BLK - 1) / SCAN_BLK)   // 98

#define XS_STRIDE 260
// dynamic smem layout (floats):
//   Bs : [2][32][128] -> 8192 floats @ 0
//   xs : [64][260]    -> 16640 floats @ 8192
//   flg: [64]         @ 24832
#define SMEM_FLOATS 24896
#define SMEM_BYTES (SMEM_FLOATS * 4)

// ---------------------------------------------------------------------------
// Device scratch
// ---------------------------------------------------------------------------
__device__ int    g_cnt [N_NODES];
__device__ int    g_cur [N_NODES];
__device__ int    g_off [N_NODES + 1];
__device__ int    g_bsum[128];
__device__ float4 g_edata[N_EDGES];   // {eid, src, w, pad} packed per edge

// ---------------------------------------------------------------------------
// fp32x2 packed FMA helpers
// ---------------------------------------------------------------------------
typedef unsigned long long ull;
__device__ __forceinline__ ull pack2(float lo, float hi) {
    ull r;
    asm("mov.b64 %0, {%1, %2};" : "=l"(r) : "f"(lo), "f"(hi));
    return r;
}
__device__ __forceinline__ void unpack2(ull v, float& lo, float& hi) {
    asm("mov.b64 {%0, %1}, %2;" : "=f"(lo), "=f"(hi) : "l"(v));
}
__device__ __forceinline__ void fma2(ull& acc, ull a, ull b) {
    asm("fma.rn.f32x2 %0, %1, %2, %0;" : "+l"(acc) : "l"(a), "l"(b));
}

// ---------------------------------------------------------------------------
__global__ void k_zero() {
    int i = blockIdx.x * blockDim.x + threadIdx.x;
    if (i < N_NODES) { g_cnt[i] = 0; g_cur[i] = 0; }
}

__global__ __launch_bounds__(256) void k_hist(const int* __restrict__ dst) {
    int e = blockIdx.x * blockDim.x + threadIdx.x;
    if (e < N_EDGES) atomicAdd(&g_cnt[dst[e]], 1);
}

__global__ __launch_bounds__(SCAN_BLK) void k_scan1() {
    __shared__ int warp_pfx[32];
    const int tid = threadIdx.x;
    const int i   = blockIdx.x * SCAN_BLK + tid;
    const int v   = (i < N_NODES) ? g_cnt[i] : 0;

    int x = v;
#pragma unroll
    for (int o = 1; o < 32; o <<= 1) {
        int y = __shfl_up_sync(0xffffffffu, x, o);
        if ((tid & 31) >= o) x += y;
    }
    if ((tid & 31) == 31) warp_pfx[tid >> 5] = x;
    __syncthreads();
    if (tid < 32) {
        int t = warp_pfx[tid];
        int s = t;
#pragma unroll
        for (int o = 1; o < 32; o <<= 1) {
            int y = __shfl_up_sync(0xffffffffu, s, o);
            if (tid >= o) s += y;
        }
        warp_pfx[tid] = s - t;
        if (tid == 31) g_bsum[blockIdx.x] = s;
    }
    __syncthreads();
    if (i < N_NODES) g_off[i] = (x - v) + warp_pfx[tid >> 5];
}

__global__ __launch_bounds__(128) void k_scan2() {
    __shared__ int s[128];
    const int tid = threadIdx.x;
    const int v = (tid < N_SCAN_BLOCKS) ? g_bsum[tid] : 0;
    s[tid] = v;
    __syncthreads();
#pragma unroll
    for (int o = 1; o < 128; o <<= 1) {
        int y = (tid >= o) ? s[tid - o] : 0;
        __syncthreads();
        s[tid] += y;
        __syncthreads();
    }
    if (tid < N_SCAN_BLOCKS) g_bsum[tid] = s[tid] - v;
}

__global__ void k_scan3() {
    int i = blockIdx.x * blockDim.x + threadIdx.x;
    if (i < N_NODES) g_off[i] += g_bsum[i >> 10];
    if (i == 0) g_off[N_NODES] = N_EDGES;
}

__global__ __launch_bounds__(256) void k_perm(const int* __restrict__ src,
                                              const int* __restrict__ dst,
                                              const float* __restrict__ ew) {
    int e = blockIdx.x * blockDim.x + threadIdx.x;
    if (e >= N_EDGES) return;
    const int d   = dst[e];
    const int pos = g_off[d] + atomicAdd(&g_cur[d], 1);
    g_edata[pos] = make_float4(__int_as_float(e), __int_as_float(src[e]),
                               __ldg(ew + e), 0.f);
}

// ---------------------------------------------------------------------------
// Fused gather + GEMM.  64 nodes/block, 256 threads, 2 blocks/SM.
// Phase 1: warp w gathers nodes w*8..w*8+7 into smem xs[64][260].
// Phase 2: out[64,128] = xs[64,256] @ Wcat^T + bn + flag*be   (FFMA2)
// ---------------------------------------------------------------------------
__global__ __launch_bounds__(256, 2) void k_fused(const float* __restrict__ nfeat,
                                                  const float* __restrict__ efeat,
                                                  const float* __restrict__ Wn,
                                                  const float* __restrict__ bn,
                                                  const float* __restrict__ We,
                                                  const float* __restrict__ be,
                                                  float*       __restrict__ out) {
    extern __shared__ float sm[];
    float* Bs  = sm;            // [2][32][128]
    float* xs  = sm + 8192;     // [64][260]
    float* flg = sm + 24832;    // [64]

    const int tid  = threadIdx.x;
    const int n0   = blockIdx.x * 64;
    const int wid  = tid >> 5;
    const int lane = tid & 31;

    // ---------------- Phase 1: gather ----------------
#pragma unroll 1
    for (int r = 0; r < 8; r++) {
        const int m = wid * 8 + r;
        const int n = n0 + m;
        float4 x1 = make_float4(0.f, 0.f, 0.f, 0.f);
        float4 x2 = make_float4(0.f, 0.f, 0.f, 0.f);
        float  deg = 0.f;
        if (n < N_NODES) {
            const int beg = __ldg(g_off + n);
            const int end = __ldg(g_off + n + 1);
            deg = (float)(end - beg);

            float4 accn = make_float4(0.f, 0.f, 0.f, 0.f);
            float4 acce = make_float4(0.f, 0.f, 0.f, 0.f);

            int i = beg;
            for (; i + 3 < end; i += 4) {
                const float4 p0 = __ldg(g_edata + i + 0);
                const float4 p1 = __ldg(g_edata + i + 1);
                const float4 p2 = __ldg(g_edata + i + 2);
                const float4 p3 = __ldg(g_edata + i + 3);
                const int e0 = __float_as_int(p0.x), s0 = __float_as_int(p0.y);
                const int e1 = __float_as_int(p1.x), s1 = __float_as_int(p1.y);
                const int e2 = __float_as_int(p2.x), s2 = __float_as_int(p2.y);
                const int e3 = __float_as_int(p3.x), s3 = __float_as_int(p3.y);
                const float w0 = p0.z, w1 = p1.z, w2 = p2.z, w3 = p3.z;

                const float4 f0 = __ldg(reinterpret_cast<const float4*>(efeat + (size_t)e0 * D) + lane);
                const float4 f1 = __ldg(reinterpret_cast<const float4*>(efeat + (size_t)e1 * D) + lane);
                const float4 f2 = __ldg(reinterpret_cast<const float4*>(efeat + (size_t)e2 * D) + lane);
                const float4 f3 = __ldg(reinterpret_cast<const float4*>(efeat + (size_t)e3 * D) + lane);
                const float4 m0 = __ldg(reinterpret_cast<const float4*>(nfeat + (size_t)s0 * D) + lane);
                const float4 m1 = __ldg(reinterpret_cast<const float4*>(nfeat + (size_t)s1 * D) + lane);
                const float4 m2 = __ldg(reinterpret_cast<const float4*>(nfeat + (size_t)s2 * D) + lane);
                const float4 m3 = __ldg(reinterpret_cast<const float4*>(nfeat + (size_t)s3 * D) + lane);

                acce.x += (f0.x + f1.x) + (f2.x + f3.x);
                acce.y += (f0.y + f1.y) + (f2.y + f3.y);
                acce.z += (f0.z + f1.z) + (f2.z + f3.z);
                acce.w += (f0.w + f1.w) + (f2.w + f3.w);
                accn.x += (w0 * m0.x + w1 * m1.x) + (w2 * m2.x + w3 * m3.x);
                accn.y += (w0 * m0.y + w1 * m1.y) + (w2 * m2.y + w3 * m3.y);
                accn.z += (w0 * m0.z + w1 * m1.z) + (w2 * m2.z + w3 * m3.z);
                accn.w += (w0 * m0.w + w1 * m1.w) + (w2 * m2.w + w3 * m3.w);
            }
            for (; i < end; i++) {
                const float4 p = __ldg(g_edata + i);
                const int e = __float_as_int(p.x), s = __float_as_int(p.y);
                const float w = p.z;
                const float4 f = __ldg(reinterpret_cast<const float4*>(efeat + (size_t)e * D) + lane);
                const float4 mm = __ldg(reinterpret_cast<const float4*>(nfeat + (size_t)s * D) + lane);
                acce.x += f.x; acce.y += f.y; acce.z += f.z; acce.w += f.w;
                accn.x += w * mm.x; accn.y += w * mm.y; accn.z += w * mm.z; accn.w += w * mm.w;
            }

            const float rd1 = 1.f / (deg + 1.f);
            const float rd2 = 1.f / fmaxf(deg, 1.f);
            const float4 self = __ldg(reinterpret_cast<const float4*>(nfeat + (size_t)n * D) + lane);
            x1.x = (accn.x + 2.f * self.x) * rd1;
            x1.y = (accn.y + 2.f * self.y) * rd1;
            x1.z = (accn.z + 2.f * self.z) * rd1;
            x1.w = (accn.w + 2.f * self.w) * rd1;
            x2.x = acce.x * rd2; x2.y = acce.y * rd2;
            x2.z = acce.z * rd2; x2.w = acce.w * rd2;
        }
        *reinterpret_cast<float4*>(&xs[m * XS_STRIDE + lane * 4])       = x1;
        *reinterpret_cast<float4*>(&xs[m * XS_STRIDE + 128 + lane * 4]) = x2;
        if (lane == 0) flg[m] = (deg > 0.f) ? 1.f : 0.f;
    }
    __syncthreads();

    // ---------------- Phase 2: GEMM ----------------
    ull acc2[4][4];
#pragma unroll
    for (int p = 0; p < 4; p++)
#pragma unroll
        for (int j = 0; j < 4; j++) acc2[p][j] = 0ull;

    const int tr = wid;          // rows tr*8 .. tr*8+7
    const int tc = lane;         // cols tc*4 .. tc*4+3

    // B loader mapping: 4 float4 per thread
    const int wj = tid >> 1;
    const int wv = tid & 1;

    float4 rb[4];
    auto loadB = [&](int k0) {
        const bool  half1 = (k0 < 128);
        const float* Wp   = half1 ? Wn : We;
        const int   kb    = half1 ? k0 : (k0 - 128);
#pragma unroll
        for (int q = 0; q < 4; q++) {
            const int kk = wv * 16 + q * 4;
            rb[q] = __ldg(reinterpret_cast<const float4*>(Wp + (size_t)wj * D + kb + kk));
        }
    };
    auto storeB = [&](int buf) {
        float* B = Bs + buf * 4096;
#pragma unroll
        for (int q = 0; q < 4; q++) {
            const int kk = wv * 16 + q * 4;
            B[(kk + 0) * 128 + wj] = rb[q].x;
            B[(kk + 1) * 128 + wj] = rb[q].y;
            B[(kk + 2) * 128 + wj] = rb[q].z;
            B[(kk + 3) * 128 + wj] = rb[q].w;
        }
    };

    loadB(0);
    storeB(0);
    __syncthreads();

#pragma unroll 1
    for (int it = 0; it < 8; it++) {
        const int buf = it & 1;
        const int k0  = it * 32;
        if (it < 7) loadB((it + 1) * 32);

        const float* B = Bs + buf * 4096;
#pragma unroll
        for (int kq = 0; kq < 32; kq += 4) {
            float4 av[8];
#pragma unroll
            for (int i2 = 0; i2 < 8; i2++)
                av[i2] = *reinterpret_cast<const float4*>(&xs[(tr * 8 + i2) * XS_STRIDE + k0 + kq]);
            const float* avf = reinterpret_cast<const float*>(av);
#pragma unroll
            for (int j = 0; j < 4; j++) {
                const float4 b4 = *reinterpret_cast<const float4*>(&B[(kq + j) * 128 + tc * 4]);
                const ull bb0 = pack2(b4.x, b4.x);
                const ull bb1 = pack2(b4.y, b4.y);
                const ull bb2 = pack2(b4.z, b4.z);
                const ull bb3 = pack2(b4.w, b4.w);
#pragma unroll
                for (int p = 0; p < 4; p++) {
                    const ull ap = pack2(avf[(2 * p) * 4 + j], avf[(2 * p + 1) * 4 + j]);
                    fma2(acc2[p][0], ap, bb0);
                    fma2(acc2[p][1], ap, bb1);
                    fma2(acc2[p][2], ap, bb2);
                    fma2(acc2[p][3], ap, bb3);
                }
            }
        }

        if (it < 7) {
            storeB(buf ^ 1);
            __syncthreads();
        }
    }

    // ---------------- epilogue ----------------
    const float4 bnv = __ldg(reinterpret_cast<const float4*>(bn + tc * 4));
    const float4 bev = __ldg(reinterpret_cast<const float4*>(be + tc * 4));
#pragma unroll
    for (int p = 0; p < 4; p++) {
        float lo[4], hi[4];
#pragma unroll
        for (int j = 0; j < 4; j++) unpack2(acc2[p][j], lo[j], hi[j]);

        const int r0 = n0 + tr * 8 + 2 * p;
#pragma unroll
        for (int h = 0; h < 2; h++) {
            const int n = r0 + h;
            if (n < N_NODES) {
                const float f = flg[tr * 8 + 2 * p + h];
                const float* a = h ? hi : lo;
                float4 o;
                o.x = a[0] + bnv.x + f * bev.x;
                o.y = a[1] + bnv.y + f * bev.y;
                o.z = a[2] + bnv.z + f * bev.z;
                o.w = a[3] + bnv.w + f * bev.w;
                *reinterpret_cast<float4*>(out + (size_t)n * D + tc * 4) = o;
            }
        }
    }
}

// ---------------------------------------------------------------------------
extern "C" void kernel_launch(void* const* d_in, const int* in_sizes, int n_in,
                              void* d_out, int out_size) {
    const float* nfeat = (const float*)d_in[0];
    const float* efeat = (const float*)d_in[1];
    const float* ew    = (const float*)d_in[2];
    const float* Wn    = (const float*)d_in[3];
    const float* bn    = (const float*)d_in[4];
    const float* We    = (const float*)d_in[5];
    const float* be    = (const float*)d_in[6];
    const int*   src   = (const int*)d_in[7];
    const int*   dst   = (const int*)d_in[8];
    float*       out   = (float*)d_out;

    (void)in_sizes; (void)n_in; (void)out_size;

    cudaFuncSetAttribute(k_fused, cudaFuncAttributeMaxDynamicSharedMemorySize, SMEM_BYTES);

    k_zero <<<(N_NODES + 255) / 256, 256>>>();
    k_hist <<<(N_EDGES + 255) / 256, 256>>>(dst);
    k_scan1<<<N_SCAN_BLOCKS, SCAN_BLK>>>();
    k_scan2<<<1, 128>>>();
    k_scan3<<<(N_NODES + 255) / 256, 256>>>();
    k_perm <<<(N_EDGES + 255) / 256, 256>>>(src, dst, ew);
    k_fused<<<(N_NODES + 63) / 64, 256, SMEM_BYTES>>>(nfeat, efeat, Wn, bn, We, be, out);
}